// round 1
// baseline (speedup 1.0000x reference)
#include <cuda_runtime.h>
#include <math.h>

#define T  8192
#define H  512
#define E  8
#define IM 1024
#define IS 2048

// ---------------- device scratch (allocation-free) ----------------
__device__ int   g_cnt[E];
__device__ int   g_tok[E * T];
__device__ float g_wt[E * T];
__device__ float g_sgate[T];
__device__ float g_h[(size_t)E * T * IM];   // routed SwiGLU activations (padded segments)
__device__ float g_hs[(size_t)T * IS];      // shared-expert SwiGLU activations

// ---------------- small kernels ----------------
__global__ void k_zero_cnt() {
    if (threadIdx.x < E) g_cnt[threadIdx.x] = 0;
}

// One warp per token: router logits, softmax, top-2 dispatch, shared sigmoid gate.
__global__ void k_router(const float* __restrict__ x, const float* __restrict__ gw,
                         const float* __restrict__ sgw, float* __restrict__ logits_out) {
    const int warp = threadIdx.x >> 5;
    const int lane = threadIdx.x & 31;
    const int t = blockIdx.x * 8 + warp;
    if (t >= T) return;

    float xv[16];
    const float* xr = x + (size_t)t * H;
#pragma unroll
    for (int i = 0; i < 16; i++) xv[i] = xr[lane + 32 * i];

    float l[E];
#pragma unroll
    for (int e = 0; e < E; e++) {
        const float* w = gw + (size_t)e * H;
        float s = 0.f;
#pragma unroll
        for (int i = 0; i < 16; i++) s = fmaf(xv[i], w[lane + 32 * i], s);
#pragma unroll
        for (int off = 16; off > 0; off >>= 1) s += __shfl_xor_sync(0xffffffffu, s, off);
        l[e] = s;
    }
    // shared gate dot
    float sd = 0.f;
#pragma unroll
    for (int i = 0; i < 16; i++) sd = fmaf(xv[i], sgw[lane + 32 * i], sd);
#pragma unroll
    for (int off = 16; off > 0; off >>= 1) sd += __shfl_xor_sync(0xffffffffu, sd, off);

    if (lane == 0) {
        if (logits_out) {
#pragma unroll
            for (int e = 0; e < E; e++) logits_out[(size_t)t * E + e] = l[e];
        }
        // softmax in fp32
        float m = l[0];
#pragma unroll
        for (int e = 1; e < E; e++) m = fmaxf(m, l[e]);
        float p[E], s = 0.f;
#pragma unroll
        for (int e = 0; e < E; e++) { p[e] = expf(l[e] - m); s += p[e]; }
        float inv = 1.f / s;
#pragma unroll
        for (int e = 0; e < E; e++) p[e] *= inv;
        // top-2 (first occurrence on ties, like lax.top_k)
        int i1 = 0;
#pragma unroll
        for (int e = 1; e < E; e++) if (p[e] > p[i1]) i1 = e;
        int i2 = (i1 == 0) ? 1 : 0;
#pragma unroll
        for (int e = 0; e < E; e++) if (e != i1 && p[e] > p[i2]) i2 = e;

        int pos1 = atomicAdd(&g_cnt[i1], 1);
        g_tok[i1 * T + pos1] = t; g_wt[i1 * T + pos1] = p[i1];
        int pos2 = atomicAdd(&g_cnt[i2], 1);
        g_tok[i2 * T + pos2] = t; g_wt[i2 * T + pos2] = p[i2];

        g_sgate[t] = 1.f / (1.f + expf(-sd));
    }
}

// ---------------- tiled GEMM kernels: 64x64 tile, BK=16, 256 threads, 4x4 micro ----------------

// Routed up-projection: h = silu(Xg @ w1e^T) * (Xg @ w3e^T), gathered rows.
__global__ void k_up_routed(const float* __restrict__ x,
                            const float* __restrict__ w1,
                            const float* __restrict__ w3) {
    const int e = blockIdx.z;
    const int ne = g_cnt[e];
    const int row0 = blockIdx.y * 64;
    if (row0 >= ne) return;
    const int col0 = blockIdx.x * 64;
    const int* toks = g_tok + e * T;

    __shared__ __align__(16) float As[16][68];
    __shared__ __align__(16) float B1s[16][68];
    __shared__ __align__(16) float B3s[16][68];

    const int tid = threadIdx.x;
    const int tx = tid & 15, ty = tid >> 4;
    const int lk = tid & 15, lr = tid >> 4;

    float acc1[4][4], acc3[4][4];
#pragma unroll
    for (int i = 0; i < 4; i++)
#pragma unroll
        for (int j = 0; j < 4; j++) { acc1[i][j] = 0.f; acc3[i][j] = 0.f; }

    int arow[4];
#pragma unroll
    for (int q = 0; q < 4; q++) {
        int gr = row0 + lr + q * 16;
        arow[q] = (gr < ne) ? toks[gr] : -1;
    }
    const float* w1b = w1 + (size_t)e * IM * H;
    const float* w3b = w3 + (size_t)e * IM * H;

    for (int k0 = 0; k0 < H; k0 += 16) {
#pragma unroll
        for (int q = 0; q < 4; q++) {
            int r = lr + q * 16;
            As[lk][r]  = (arow[q] >= 0) ? x[(size_t)arow[q] * H + k0 + lk] : 0.f;
            B1s[lk][r] = w1b[(size_t)(col0 + r) * H + k0 + lk];
            B3s[lk][r] = w3b[(size_t)(col0 + r) * H + k0 + lk];
        }
        __syncthreads();
#pragma unroll
        for (int kk = 0; kk < 16; kk++) {
            const float4 av  = *(const float4*)&As[kk][ty * 4];
            const float4 bv1 = *(const float4*)&B1s[kk][tx * 4];
            const float4 bv3 = *(const float4*)&B3s[kk][tx * 4];
            const float a[4]  = {av.x, av.y, av.z, av.w};
            const float b1[4] = {bv1.x, bv1.y, bv1.z, bv1.w};
            const float b3[4] = {bv3.x, bv3.y, bv3.z, bv3.w};
#pragma unroll
            for (int i = 0; i < 4; i++)
#pragma unroll
                for (int j = 0; j < 4; j++) {
                    acc1[i][j] = fmaf(a[i], b1[j], acc1[i][j]);
                    acc3[i][j] = fmaf(a[i], b3[j], acc3[i][j]);
                }
        }
        __syncthreads();
    }
#pragma unroll
    for (int i = 0; i < 4; i++) {
        int gr = row0 + ty * 4 + i;
        if (gr >= ne) continue;
        size_t ob = ((size_t)e * T + gr) * IM + col0 + tx * 4;
#pragma unroll
        for (int j = 0; j < 4; j++) {
            float v = acc1[i][j];
            g_h[ob + j] = (v / (1.f + __expf(-v))) * acc3[i][j];
        }
    }
}

// Routed down-projection + weighted scatter-add into out.
__global__ void k_down_routed(const float* __restrict__ w2, float* __restrict__ out) {
    const int e = blockIdx.z;
    const int ne = g_cnt[e];
    const int row0 = blockIdx.y * 64;
    if (row0 >= ne) return;
    const int col0 = blockIdx.x * 64;

    __shared__ __align__(16) float As[16][68];
    __shared__ __align__(16) float Bs[16][68];

    const int tid = threadIdx.x;
    const int tx = tid & 15, ty = tid >> 4;
    const int lk = tid & 15, lr = tid >> 4;

    float acc[4][4];
#pragma unroll
    for (int i = 0; i < 4; i++)
#pragma unroll
        for (int j = 0; j < 4; j++) acc[i][j] = 0.f;

    const float* ab = g_h + (size_t)e * T * IM;
    const float* bb = w2 + (size_t)e * H * IM;

    for (int k0 = 0; k0 < IM; k0 += 16) {
#pragma unroll
        for (int q = 0; q < 4; q++) {
            int r = lr + q * 16;
            As[lk][r] = (row0 + r < ne) ? ab[(size_t)(row0 + r) * IM + k0 + lk] : 0.f;
            Bs[lk][r] = bb[(size_t)(col0 + r) * IM + k0 + lk];
        }
        __syncthreads();
#pragma unroll
        for (int kk = 0; kk < 16; kk++) {
            const float4 av = *(const float4*)&As[kk][ty * 4];
            const float4 bv = *(const float4*)&Bs[kk][tx * 4];
            const float a[4] = {av.x, av.y, av.z, av.w};
            const float b[4] = {bv.x, bv.y, bv.z, bv.w};
#pragma unroll
            for (int i = 0; i < 4; i++)
#pragma unroll
                for (int j = 0; j < 4; j++) acc[i][j] = fmaf(a[i], b[j], acc[i][j]);
        }
        __syncthreads();
    }
#pragma unroll
    for (int i = 0; i < 4; i++) {
        int gr = row0 + ty * 4 + i;
        if (gr >= ne) continue;
        int t  = g_tok[e * T + gr];
        float wt = g_wt[e * T + gr];
        size_t ob = (size_t)t * H + col0 + tx * 4;
#pragma unroll
        for (int j = 0; j < 4; j++) atomicAdd(&out[ob + j], wt * acc[i][j]);
    }
}

// Shared up-projection: hs = silu(x @ sw1^T) * (x @ sw3^T)
__global__ void k_up_shared(const float* __restrict__ x,
                            const float* __restrict__ w1,
                            const float* __restrict__ w3) {
    const int row0 = blockIdx.y * 64;
    const int col0 = blockIdx.x * 64;

    __shared__ __align__(16) float As[16][68];
    __shared__ __align__(16) float B1s[16][68];
    __shared__ __align__(16) float B3s[16][68];

    const int tid = threadIdx.x;
    const int tx = tid & 15, ty = tid >> 4;
    const int lk = tid & 15, lr = tid >> 4;

    float acc1[4][4], acc3[4][4];
#pragma unroll
    for (int i = 0; i < 4; i++)
#pragma unroll
        for (int j = 0; j < 4; j++) { acc1[i][j] = 0.f; acc3[i][j] = 0.f; }

    for (int k0 = 0; k0 < H; k0 += 16) {
#pragma unroll
        for (int q = 0; q < 4; q++) {
            int r = lr + q * 16;
            As[lk][r]  = x[(size_t)(row0 + r) * H + k0 + lk];
            B1s[lk][r] = w1[(size_t)(col0 + r) * H + k0 + lk];
            B3s[lk][r] = w3[(size_t)(col0 + r) * H + k0 + lk];
        }
        __syncthreads();
#pragma unroll
        for (int kk = 0; kk < 16; kk++) {
            const float4 av  = *(const float4*)&As[kk][ty * 4];
            const float4 bv1 = *(const float4*)&B1s[kk][tx * 4];
            const float4 bv3 = *(const float4*)&B3s[kk][tx * 4];
            const float a[4]  = {av.x, av.y, av.z, av.w};
            const float b1[4] = {bv1.x, bv1.y, bv1.z, bv1.w};
            const float b3[4] = {bv3.x, bv3.y, bv3.z, bv3.w};
#pragma unroll
            for (int i = 0; i < 4; i++)
#pragma unroll
                for (int j = 0; j < 4; j++) {
                    acc1[i][j] = fmaf(a[i], b1[j], acc1[i][j]);
                    acc3[i][j] = fmaf(a[i], b3[j], acc3[i][j]);
                }
        }
        __syncthreads();
    }
#pragma unroll
    for (int i = 0; i < 4; i++) {
        size_t ob = (size_t)(row0 + ty * 4 + i) * IS + col0 + tx * 4;
#pragma unroll
        for (int j = 0; j < 4; j++) {
            float v = acc1[i][j];
            g_hs[ob + j] = (v / (1.f + __expf(-v))) * acc3[i][j];
        }
    }
}

// Final: out += sgate * (hs @ sw2^T)
__global__ void k_final(const float* __restrict__ w2s, float* __restrict__ out) {
    const int row0 = blockIdx.y * 64;
    const int col0 = blockIdx.x * 64;

    __shared__ __align__(16) float As[16][68];
    __shared__ __align__(16) float Bs[16][68];

    const int tid = threadIdx.x;
    const int tx = tid & 15, ty = tid >> 4;
    const int lk = tid & 15, lr = tid >> 4;

    float acc[4][4];
#pragma unroll
    for (int i = 0; i < 4; i++)
#pragma unroll
        for (int j = 0; j < 4; j++) acc[i][j] = 0.f;

    for (int k0 = 0; k0 < IS; k0 += 16) {
#pragma unroll
        for (int q = 0; q < 4; q++) {
            int r = lr + q * 16;
            As[lk][r] = g_hs[(size_t)(row0 + r) * IS + k0 + lk];
            Bs[lk][r] = w2s[(size_t)(col0 + r) * IS + k0 + lk];
        }
        __syncthreads();
#pragma unroll
        for (int kk = 0; kk < 16; kk++) {
            const float4 av = *(const float4*)&As[kk][ty * 4];
            const float4 bv = *(const float4*)&Bs[kk][tx * 4];
            const float a[4] = {av.x, av.y, av.z, av.w};
            const float b[4] = {bv.x, bv.y, bv.z, bv.w};
#pragma unroll
            for (int i = 0; i < 4; i++)
#pragma unroll
                for (int j = 0; j < 4; j++) acc[i][j] = fmaf(a[i], b[j], acc[i][j]);
        }
        __syncthreads();
    }
#pragma unroll
    for (int i = 0; i < 4; i++) {
        int t = row0 + ty * 4 + i;
        float sg = g_sgate[t];
        size_t ob = (size_t)t * H + col0 + tx * 4;
#pragma unroll
        for (int j = 0; j < 4; j++) out[ob + j] += sg * acc[i][j];
    }
}

// ---------------- launcher ----------------
extern "C" void kernel_launch(void* const* d_in, const int* in_sizes, int n_in,
                              void* d_out, int out_size) {
    const float* x   = (const float*)d_in[0];
    const float* gw  = (const float*)d_in[1];
    const float* w1  = (const float*)d_in[2];
    const float* w2  = (const float*)d_in[3];
    const float* w3  = (const float*)d_in[4];
    const float* sw1 = (const float*)d_in[5];
    const float* sw2 = (const float*)d_in[6];
    const float* sw3 = (const float*)d_in[7];
    const float* sgw = (const float*)d_in[8];

    float* out = (float*)d_out;
    float* logits = (out_size >= (int)((size_t)T * H + (size_t)T * E))
                        ? out + (size_t)T * H : nullptr;

    k_zero_cnt<<<1, 32>>>();
    size_t nz = (size_t)T * H;
    if ((size_t)out_size < nz) nz = (size_t)out_size;
    cudaMemsetAsync(d_out, 0, nz * sizeof(float), 0);

    k_router<<<T / 8, 256>>>(x, gw, sgw, logits);

    k_up_routed  <<<dim3(IM / 64, T / 64, E), 256>>>(x, w1, w3);
    k_down_routed<<<dim3(H  / 64, T / 64, E), 256>>>(w2, out);

    k_up_shared<<<dim3(IS / 64, T / 64), 256>>>(x, sw1, sw3);
    k_final    <<<dim3(H  / 64, T / 64), 256>>>(sw2, out);
}

// round 2
// speedup vs baseline: 3.0212x; 3.0212x over previous
#include <cuda_runtime.h>
#include <math.h>
#include <stdint.h>

#define T  8192
#define H  512
#define E  8
#define IM 1024
#define IS 2048

#define BK   32
#define ASTR 36   // BK + 4 pad (conflict-free fragment LDS)

// ---------------- device scratch (allocation-free) ----------------
__device__ int   g_cnt[E];
__device__ int   g_tok[E * T];
__device__ float g_wt[E * T];
__device__ float g_sgate[T];
__device__ float g_h[(size_t)E * T * IM];   // routed SwiGLU activations
__device__ float g_hs[(size_t)T * IS];      // shared-expert SwiGLU activations

// ---------------- helpers ----------------
__device__ __forceinline__ uint32_t f2tf(float f) {
    uint32_t u; asm("cvt.rna.tf32.f32 %0, %1;" : "=r"(u) : "f"(f)); return u;
}

__device__ __forceinline__ void mma8(float* c,
        uint32_t a0, uint32_t a1, uint32_t a2, uint32_t a3,
        uint32_t b0, uint32_t b1) {
    asm volatile(
        "mma.sync.aligned.m16n8k8.row.col.f32.tf32.tf32.f32 "
        "{%0,%1,%2,%3}, {%4,%5,%6,%7}, {%8,%9}, {%0,%1,%2,%3};"
        : "+f"(c[0]), "+f"(c[1]), "+f"(c[2]), "+f"(c[3])
        : "r"(a0), "r"(a1), "r"(a2), "r"(a3), "r"(b0), "r"(b1));
}

__device__ __forceinline__ float silu_f(float v) {
    return v / (1.f + __expf(-v));
}

// ---------------- small kernels ----------------
__global__ void k_zero_cnt() {
    if (threadIdx.x < E) g_cnt[threadIdx.x] = 0;
}

// One warp per token: router logits (fp32), softmax, top-2 dispatch, sigmoid gate.
__global__ void k_router(const float* __restrict__ x, const float* __restrict__ gw,
                         const float* __restrict__ sgw, float* __restrict__ logits_out) {
    const int warp = threadIdx.x >> 5;
    const int lane = threadIdx.x & 31;
    const int t = blockIdx.x * 8 + warp;
    if (t >= T) return;

    float xv[16];
    const float* xr = x + (size_t)t * H;
#pragma unroll
    for (int i = 0; i < 16; i++) xv[i] = xr[lane + 32 * i];

    float l[E];
#pragma unroll
    for (int e = 0; e < E; e++) {
        const float* w = gw + (size_t)e * H;
        float s = 0.f;
#pragma unroll
        for (int i = 0; i < 16; i++) s = fmaf(xv[i], w[lane + 32 * i], s);
#pragma unroll
        for (int off = 16; off > 0; off >>= 1) s += __shfl_xor_sync(0xffffffffu, s, off);
        l[e] = s;
    }
    float sd = 0.f;
#pragma unroll
    for (int i = 0; i < 16; i++) sd = fmaf(xv[i], sgw[lane + 32 * i], sd);
#pragma unroll
    for (int off = 16; off > 0; off >>= 1) sd += __shfl_xor_sync(0xffffffffu, sd, off);

    if (lane == 0) {
        if (logits_out) {
#pragma unroll
            for (int e = 0; e < E; e++) logits_out[(size_t)t * E + e] = l[e];
        }
        float m = l[0];
#pragma unroll
        for (int e = 1; e < E; e++) m = fmaxf(m, l[e]);
        float p[E], s = 0.f;
#pragma unroll
        for (int e = 0; e < E; e++) { p[e] = expf(l[e] - m); s += p[e]; }
        float inv = 1.f / s;
#pragma unroll
        for (int e = 0; e < E; e++) p[e] *= inv;
        int i1 = 0;
#pragma unroll
        for (int e = 1; e < E; e++) if (p[e] > p[i1]) i1 = e;
        int i2 = (i1 == 0) ? 1 : 0;
#pragma unroll
        for (int e = 0; e < E; e++) if (e != i1 && p[e] > p[i2]) i2 = e;

        int pos1 = atomicAdd(&g_cnt[i1], 1);
        g_tok[i1 * T + pos1] = t; g_wt[i1 * T + pos1] = p[i1];
        int pos2 = atomicAdd(&g_cnt[i2], 1);
        g_tok[i2 * T + pos2] = t; g_wt[i2 * T + pos2] = p[i2];

        g_sgate[t] = 1.f / (1.f + expf(-sd));
    }
}

// =====================================================================
// TF32 tensor-core GEMM kernels
// Common: 256 threads = 8 warps laid out 4(m) x 2(n).
// =====================================================================

// Routed up-projection (dual GEMM): h = silu(Xg @ w1e^T) * (Xg @ w3e^T)
// BM=128, BN=64, warp tile 32x32
__global__ __launch_bounds__(256) void k_up_routed_tc(
        const float* __restrict__ x,
        const float* __restrict__ w1,
        const float* __restrict__ w3) {
    const int e = blockIdx.z;
    const int ne = g_cnt[e];
    const int row0 = blockIdx.y * 128;
    if (row0 >= ne) return;
    const int col0 = blockIdx.x * 64;
    const int* toks = g_tok + e * T;

    __shared__ uint32_t As[128 * ASTR];
    __shared__ uint32_t B1s[64 * ASTR];
    __shared__ uint32_t B3s[64 * ASTR];

    const int tid = threadIdx.x;
    const int lane = tid & 31, wid = tid >> 5;
    const int qid = lane >> 2, tig = lane & 3;
    const int wm = wid & 3, wn = wid >> 2;

    const int lr = tid >> 3;          // loader row 0..31
    const int lc = (tid & 7) * 4;     // loader col (float4)

    int atok[4];
#pragma unroll
    for (int q = 0; q < 4; q++) {
        int r = row0 + lr + q * 32;
        atok[q] = (r < ne) ? toks[r] : -1;
    }

    const float* w1b = w1 + (size_t)e * IM * H + (size_t)col0 * H;
    const float* w3b = w3 + (size_t)e * IM * H + (size_t)col0 * H;

    float acc1[2][4][4], acc3[2][4][4];
#pragma unroll
    for (int mi = 0; mi < 2; mi++)
#pragma unroll
        for (int ni = 0; ni < 4; ni++)
#pragma unroll
            for (int r = 0; r < 4; r++) { acc1[mi][ni][r] = 0.f; acc3[mi][ni][r] = 0.f; }

    for (int k0 = 0; k0 < H; k0 += BK) {
#pragma unroll
        for (int q = 0; q < 4; q++) {
            float4 v = make_float4(0.f, 0.f, 0.f, 0.f);
            if (atok[q] >= 0) v = *(const float4*)(x + (size_t)atok[q] * H + k0 + lc);
            uint32_t* p = &As[(lr + q * 32) * ASTR + lc];
            p[0] = f2tf(v.x); p[1] = f2tf(v.y); p[2] = f2tf(v.z); p[3] = f2tf(v.w);
        }
#pragma unroll
        for (int q = 0; q < 2; q++) {
            int r = lr + q * 32;
            float4 v1 = *(const float4*)(w1b + (size_t)r * H + k0 + lc);
            float4 v3 = *(const float4*)(w3b + (size_t)r * H + k0 + lc);
            uint32_t* p1 = &B1s[r * ASTR + lc];
            p1[0] = f2tf(v1.x); p1[1] = f2tf(v1.y); p1[2] = f2tf(v1.z); p1[3] = f2tf(v1.w);
            uint32_t* p3 = &B3s[r * ASTR + lc];
            p3[0] = f2tf(v3.x); p3[1] = f2tf(v3.y); p3[2] = f2tf(v3.z); p3[3] = f2tf(v3.w);
        }
        __syncthreads();
#pragma unroll
        for (int ks = 0; ks < BK / 8; ks++) {
            const int kk = ks * 8 + tig;
            uint32_t a[2][4];
#pragma unroll
            for (int mi = 0; mi < 2; mi++) {
                int mb = wm * 32 + mi * 16;
                a[mi][0] = As[(mb + qid) * ASTR + kk];
                a[mi][1] = As[(mb + qid + 8) * ASTR + kk];
                a[mi][2] = As[(mb + qid) * ASTR + kk + 4];
                a[mi][3] = As[(mb + qid + 8) * ASTR + kk + 4];
            }
#pragma unroll
            for (int ni = 0; ni < 4; ni++) {
                int nb = (wn * 32 + ni * 8 + qid) * ASTR;
                uint32_t b10 = B1s[nb + kk], b11 = B1s[nb + kk + 4];
                uint32_t b30 = B3s[nb + kk], b31 = B3s[nb + kk + 4];
#pragma unroll
                for (int mi = 0; mi < 2; mi++) {
                    mma8(acc1[mi][ni], a[mi][0], a[mi][1], a[mi][2], a[mi][3], b10, b11);
                    mma8(acc3[mi][ni], a[mi][0], a[mi][1], a[mi][2], a[mi][3], b30, b31);
                }
            }
        }
        __syncthreads();
    }
#pragma unroll
    for (int mi = 0; mi < 2; mi++) {
        int rbase = row0 + wm * 32 + mi * 16 + qid;
#pragma unroll
        for (int half = 0; half < 2; half++) {
            int r = rbase + half * 8;
            if (r >= ne) continue;
            float* orow = g_h + ((size_t)e * T + r) * IM + col0 + wn * 32;
#pragma unroll
            for (int ni = 0; ni < 4; ni++) {
                float v1a = acc1[mi][ni][half * 2], v1b = acc1[mi][ni][half * 2 + 1];
                float v3a = acc3[mi][ni][half * 2], v3b = acc3[mi][ni][half * 2 + 1];
                int c = ni * 8 + 2 * tig;
                orow[c]     = silu_f(v1a) * v3a;
                orow[c + 1] = silu_f(v1b) * v3b;
            }
        }
    }
}

// Shared up-projection (dual GEMM): hs = silu(x @ sw1^T) * (x @ sw3^T)
__global__ __launch_bounds__(256) void k_up_shared_tc(
        const float* __restrict__ x,
        const float* __restrict__ w1,
        const float* __restrict__ w3) {
    const int row0 = blockIdx.y * 128;
    const int col0 = blockIdx.x * 64;

    __shared__ uint32_t As[128 * ASTR];
    __shared__ uint32_t B1s[64 * ASTR];
    __shared__ uint32_t B3s[64 * ASTR];

    const int tid = threadIdx.x;
    const int lane = tid & 31, wid = tid >> 5;
    const int qid = lane >> 2, tig = lane & 3;
    const int wm = wid & 3, wn = wid >> 2;
    const int lr = tid >> 3;
    const int lc = (tid & 7) * 4;

    const float* w1b = w1 + (size_t)col0 * H;
    const float* w3b = w3 + (size_t)col0 * H;

    float acc1[2][4][4], acc3[2][4][4];
#pragma unroll
    for (int mi = 0; mi < 2; mi++)
#pragma unroll
        for (int ni = 0; ni < 4; ni++)
#pragma unroll
            for (int r = 0; r < 4; r++) { acc1[mi][ni][r] = 0.f; acc3[mi][ni][r] = 0.f; }

    for (int k0 = 0; k0 < H; k0 += BK) {
#pragma unroll
        for (int q = 0; q < 4; q++) {
            float4 v = *(const float4*)(x + (size_t)(row0 + lr + q * 32) * H + k0 + lc);
            uint32_t* p = &As[(lr + q * 32) * ASTR + lc];
            p[0] = f2tf(v.x); p[1] = f2tf(v.y); p[2] = f2tf(v.z); p[3] = f2tf(v.w);
        }
#pragma unroll
        for (int q = 0; q < 2; q++) {
            int r = lr + q * 32;
            float4 v1 = *(const float4*)(w1b + (size_t)r * H + k0 + lc);
            float4 v3 = *(const float4*)(w3b + (size_t)r * H + k0 + lc);
            uint32_t* p1 = &B1s[r * ASTR + lc];
            p1[0] = f2tf(v1.x); p1[1] = f2tf(v1.y); p1[2] = f2tf(v1.z); p1[3] = f2tf(v1.w);
            uint32_t* p3 = &B3s[r * ASTR + lc];
            p3[0] = f2tf(v3.x); p3[1] = f2tf(v3.y); p3[2] = f2tf(v3.z); p3[3] = f2tf(v3.w);
        }
        __syncthreads();
#pragma unroll
        for (int ks = 0; ks < BK / 8; ks++) {
            const int kk = ks * 8 + tig;
            uint32_t a[2][4];
#pragma unroll
            for (int mi = 0; mi < 2; mi++) {
                int mb = wm * 32 + mi * 16;
                a[mi][0] = As[(mb + qid) * ASTR + kk];
                a[mi][1] = As[(mb + qid + 8) * ASTR + kk];
                a[mi][2] = As[(mb + qid) * ASTR + kk + 4];
                a[mi][3] = As[(mb + qid + 8) * ASTR + kk + 4];
            }
#pragma unroll
            for (int ni = 0; ni < 4; ni++) {
                int nb = (wn * 32 + ni * 8 + qid) * ASTR;
                uint32_t b10 = B1s[nb + kk], b11 = B1s[nb + kk + 4];
                uint32_t b30 = B3s[nb + kk], b31 = B3s[nb + kk + 4];
#pragma unroll
                for (int mi = 0; mi < 2; mi++) {
                    mma8(acc1[mi][ni], a[mi][0], a[mi][1], a[mi][2], a[mi][3], b10, b11);
                    mma8(acc3[mi][ni], a[mi][0], a[mi][1], a[mi][2], a[mi][3], b30, b31);
                }
            }
        }
        __syncthreads();
    }
#pragma unroll
    for (int mi = 0; mi < 2; mi++) {
        int rbase = row0 + wm * 32 + mi * 16 + qid;
#pragma unroll
        for (int half = 0; half < 2; half++) {
            int r = rbase + half * 8;
            float* orow = g_hs + (size_t)r * IS + col0 + wn * 32;
#pragma unroll
            for (int ni = 0; ni < 4; ni++) {
                float v1a = acc1[mi][ni][half * 2], v1b = acc1[mi][ni][half * 2 + 1];
                float v3a = acc3[mi][ni][half * 2], v3b = acc3[mi][ni][half * 2 + 1];
                int c = ni * 8 + 2 * tig;
                orow[c]     = silu_f(v1a) * v3a;
                orow[c + 1] = silu_f(v1b) * v3b;
            }
        }
    }
}

// Routed down-projection + weighted scatter-add. BM=128, BN=128, warp tile 32x64.
__global__ __launch_bounds__(256) void k_down_routed_tc(
        const float* __restrict__ w2, float* __restrict__ out) {
    const int e = blockIdx.z;
    const int ne = g_cnt[e];
    const int row0 = blockIdx.y * 128;
    if (row0 >= ne) return;
    const int col0 = blockIdx.x * 128;

    __shared__ uint32_t As[128 * ASTR];
    __shared__ uint32_t Bs[128 * ASTR];

    const int tid = threadIdx.x;
    const int lane = tid & 31, wid = tid >> 5;
    const int qid = lane >> 2, tig = lane & 3;
    const int wm = wid & 3, wn = wid >> 2;
    const int lr = tid >> 3;
    const int lc = (tid & 7) * 4;

    const float* ab = g_h + (size_t)e * T * IM;
    const float* bb = w2 + (size_t)e * H * IM + (size_t)col0 * IM;

    float acc[2][8][4];
#pragma unroll
    for (int mi = 0; mi < 2; mi++)
#pragma unroll
        for (int ni = 0; ni < 8; ni++)
#pragma unroll
            for (int r = 0; r < 4; r++) acc[mi][ni][r] = 0.f;

    for (int k0 = 0; k0 < IM; k0 += BK) {
#pragma unroll
        for (int q = 0; q < 4; q++) {
            int r = lr + q * 32;
            float4 va = *(const float4*)(ab + (size_t)(row0 + r) * IM + k0 + lc);
            float4 vb = *(const float4*)(bb + (size_t)r * IM + k0 + lc);
            uint32_t* pa = &As[r * ASTR + lc];
            pa[0] = f2tf(va.x); pa[1] = f2tf(va.y); pa[2] = f2tf(va.z); pa[3] = f2tf(va.w);
            uint32_t* pb = &Bs[r * ASTR + lc];
            pb[0] = f2tf(vb.x); pb[1] = f2tf(vb.y); pb[2] = f2tf(vb.z); pb[3] = f2tf(vb.w);
        }
        __syncthreads();
#pragma unroll
        for (int ks = 0; ks < BK / 8; ks++) {
            const int kk = ks * 8 + tig;
            uint32_t a[2][4];
#pragma unroll
            for (int mi = 0; mi < 2; mi++) {
                int mb = wm * 32 + mi * 16;
                a[mi][0] = As[(mb + qid) * ASTR + kk];
                a[mi][1] = As[(mb + qid + 8) * ASTR + kk];
                a[mi][2] = As[(mb + qid) * ASTR + kk + 4];
                a[mi][3] = As[(mb + qid + 8) * ASTR + kk + 4];
            }
#pragma unroll
            for (int ni = 0; ni < 8; ni++) {
                int nb = (wn * 64 + ni * 8 + qid) * ASTR;
                uint32_t b0 = Bs[nb + kk], b1 = Bs[nb + kk + 4];
#pragma unroll
                for (int mi = 0; mi < 2; mi++)
                    mma8(acc[mi][ni], a[mi][0], a[mi][1], a[mi][2], a[mi][3], b0, b1);
            }
        }
        __syncthreads();
    }
#pragma unroll
    for (int mi = 0; mi < 2; mi++) {
        int rbase = row0 + wm * 32 + mi * 16 + qid;
#pragma unroll
        for (int half = 0; half < 2; half++) {
            int r = rbase + half * 8;
            if (r >= ne) continue;
            int t = g_tok[e * T + r];
            float wt = g_wt[e * T + r];
            float* orow = out + (size_t)t * H + col0 + wn * 64;
#pragma unroll
            for (int ni = 0; ni < 8; ni++) {
                int c = ni * 8 + 2 * tig;
                atomicAdd(&orow[c],     wt * acc[mi][ni][half * 2]);
                atomicAdd(&orow[c + 1], wt * acc[mi][ni][half * 2 + 1]);
            }
        }
    }
}

// Final: out += sgate * (hs @ sw2^T). BM=128, BN=64, warp tile 32x32.
__global__ __launch_bounds__(256) void k_final_tc(
        const float* __restrict__ w2s, float* __restrict__ out) {
    const int row0 = blockIdx.y * 128;
    const int col0 = blockIdx.x * 64;

    __shared__ uint32_t As[128 * ASTR];
    __shared__ uint32_t Bs[64 * ASTR];

    const int tid = threadIdx.x;
    const int lane = tid & 31, wid = tid >> 5;
    const int qid = lane >> 2, tig = lane & 3;
    const int wm = wid & 3, wn = wid >> 2;
    const int lr = tid >> 3;
    const int lc = (tid & 7) * 4;

    const float* bb = w2s + (size_t)col0 * IS;

    float acc[2][4][4];
#pragma unroll
    for (int mi = 0; mi < 2; mi++)
#pragma unroll
        for (int ni = 0; ni < 4; ni++)
#pragma unroll
            for (int r = 0; r < 4; r++) acc[mi][ni][r] = 0.f;

    for (int k0 = 0; k0 < IS; k0 += BK) {
#pragma unroll
        for (int q = 0; q < 4; q++) {
            float4 v = *(const float4*)(g_hs + (size_t)(row0 + lr + q * 32) * IS + k0 + lc);
            uint32_t* p = &As[(lr + q * 32) * ASTR + lc];
            p[0] = f2tf(v.x); p[1] = f2tf(v.y); p[2] = f2tf(v.z); p[3] = f2tf(v.w);
        }
#pragma unroll
        for (int q = 0; q < 2; q++) {
            int r = lr + q * 32;
            float4 v = *(const float4*)(bb + (size_t)r * IS + k0 + lc);
            uint32_t* p = &Bs[r * ASTR + lc];
            p[0] = f2tf(v.x); p[1] = f2tf(v.y); p[2] = f2tf(v.z); p[3] = f2tf(v.w);
        }
        __syncthreads();
#pragma unroll
        for (int ks = 0; ks < BK / 8; ks++) {
            const int kk = ks * 8 + tig;
            uint32_t a[2][4];
#pragma unroll
            for (int mi = 0; mi < 2; mi++) {
                int mb = wm * 32 + mi * 16;
                a[mi][0] = As[(mb + qid) * ASTR + kk];
                a[mi][1] = As[(mb + qid + 8) * ASTR + kk];
                a[mi][2] = As[(mb + qid) * ASTR + kk + 4];
                a[mi][3] = As[(mb + qid + 8) * ASTR + kk + 4];
            }
#pragma unroll
            for (int ni = 0; ni < 4; ni++) {
                int nb = (wn * 32 + ni * 8 + qid) * ASTR;
                uint32_t b0 = Bs[nb + kk], b1 = Bs[nb + kk + 4];
#pragma unroll
                for (int mi = 0; mi < 2; mi++)
                    mma8(acc[mi][ni], a[mi][0], a[mi][1], a[mi][2], a[mi][3], b0, b1);
            }
        }
        __syncthreads();
    }
#pragma unroll
    for (int mi = 0; mi < 2; mi++) {
        int rbase = row0 + wm * 32 + mi * 16 + qid;
#pragma unroll
        for (int half = 0; half < 2; half++) {
            int r = rbase + half * 8;
            float sg = g_sgate[r];
            float* orow = out + (size_t)r * H + col0 + wn * 32;
#pragma unroll
            for (int ni = 0; ni < 4; ni++) {
                int c = ni * 8 + 2 * tig;
                orow[c]     += sg * acc[mi][ni][half * 2];
                orow[c + 1] += sg * acc[mi][ni][half * 2 + 1];
            }
        }
    }
}

// ---------------- launcher ----------------
extern "C" void kernel_launch(void* const* d_in, const int* in_sizes, int n_in,
                              void* d_out, int out_size) {
    const float* x   = (const float*)d_in[0];
    const float* gw  = (const float*)d_in[1];
    const float* w1  = (const float*)d_in[2];
    const float* w2  = (const float*)d_in[3];
    const float* w3  = (const float*)d_in[4];
    const float* sw1 = (const float*)d_in[5];
    const float* sw2 = (const float*)d_in[6];
    const float* sw3 = (const float*)d_in[7];
    const float* sgw = (const float*)d_in[8];

    float* out = (float*)d_out;
    float* logits = (out_size >= (int)((size_t)T * H + (size_t)T * E))
                        ? out + (size_t)T * H : nullptr;

    k_zero_cnt<<<1, 32>>>();
    size_t nz = (size_t)T * H;
    if ((size_t)out_size < nz) nz = (size_t)out_size;
    cudaMemsetAsync(d_out, 0, nz * sizeof(float), 0);

    k_router<<<T / 8, 256>>>(x, gw, sgw, logits);

    k_up_routed_tc  <<<dim3(IM / 64,  T / 128, E), 256>>>(x, w1, w3);
    k_down_routed_tc<<<dim3(H / 128,  T / 128, E), 256>>>(w2, out);

    k_up_shared_tc<<<dim3(IS / 64, T / 128), 256>>>(x, sw1, sw3);
    k_final_tc    <<<dim3(H / 64,  T / 128), 256>>>(sw2, out);
}